// round 8
// baseline (speedup 1.0000x reference)
#include <cuda_runtime.h>
#include <cstdint>
#include <cstddef>

// Problem constants
#define TT   255
#define BB   256
#define KK   784
#define NN   40
#define MM   (TT * BB)          // 65280
#define PLANE (BB * NN)         // 10240 elements per timestep
#define OUT_HALF (TT * PLANE)   // 2,611,200

// Scratch for cur = x @ W^T   (10.44 MB, static device global: allowed)
__device__ float g_cur[(size_t)MM * NN];

// packed f32x2 FMA: d = fma(a, b, d) per lane (IEEE rn, fused)
__device__ __forceinline__ void fma2(unsigned long long& d,
                                     unsigned long long a,
                                     unsigned long long b) {
    asm("fma.rn.f32x2 %0, %1, %2, %3;" : "=l"(d) : "l"(a), "l"(b), "l"(d));
}
// packed f32x2 add (rn)
__device__ __forceinline__ unsigned long long add2(unsigned long long a,
                                                   unsigned long long b) {
    unsigned long long d;
    asm("add.rn.f32x2 %0, %1, %2;" : "=l"(d) : "l"(a), "l"(b));
    return d;
}

// ---------------------------------------------------------------------------
// Kernel 1: cur[m][n] = sum_k x[m][k] * W[n][k]
//
// Rounding scheme (bit-identical to the R7-passing kernel):
//   8 chains, chain j = fused-FMA over k ≡ j (mod 8) ascending;
//   combine: ((c0+c4)+(c1+c5)) + ((c2+c6)+(c3+c7)).
//
// NEW STRUCTURE: the 8 chains live in 8 *threads* (phase = tid&7), not one.
// The combine tree is realized exactly by butterfly shuffles xor {4,1,2}
// (adds are commutative -> lane-symmetric sums are bit-identical).
// This cuts accumulator registers 8x -> no spills.
//
// 256 threads = 8 phases x 32 workers (8 row-groups x TM=8, 4 col-groups x
// TN=10). BM=64, BN=40, BK=16, grid = 65280/64 = 1020.
// smem padded: As stride 68 floats, Ws2 stride 42 float2 -> conflict-free.
// ---------------------------------------------------------------------------
__global__ __launch_bounds__(256, 1)
void snn_gemm_kernel(const float* __restrict__ x, const float* __restrict__ W) {
    __shared__ float  As[16][68];       // [k][m], padded (bank shift 4/k)
    __shared__ float2 Ws2[16][42];      // duplicated W pairs, padded (20/k)

    const int tid   = threadIdx.x;
    const int phase = tid & 7;          // chain index 0..7
    const int ww    = tid >> 3;         // worker 0..31
    const int wrow  = ww & 7;           // 8 row groups * TM=8 -> BM=64
    const int wcol  = ww >> 3;          // 4 col groups * TN=10 -> BN=40
    const int mbase = blockIdx.x * 64;

    // acc[i][c]: rows (wrow*8 + 2i, +2i+1) packed, col wcol*10+c, THIS phase's chain
    unsigned long long acc[4][10];
    #pragma unroll
    for (int i = 0; i < 4; ++i)
        #pragma unroll
        for (int c = 0; c < 10; ++c) acc[i][c] = 0ULL;

    for (int k0 = 0; k0 < KK; k0 += 16) {
        __syncthreads();   // previous chunk's compute done before overwrite

        // Load A tile: 64 rows x 16 k = 256 float4; 1 per thread (coalesced).
        {
            int row = tid >> 2;
            int q   = tid & 3;
            float4 v = *reinterpret_cast<const float4*>(
                x + (size_t)(mbase + row) * KK + k0 + q * 4);
            As[q * 4 + 0][row] = v.x;
            As[q * 4 + 1][row] = v.y;
            As[q * 4 + 2][row] = v.z;
            As[q * 4 + 3][row] = v.w;
        }
        // Load W tile: 40 n x 16 k = 640, duplicated into float2
        #pragma unroll
        for (int p = 0; p < 3; ++p) {
            int idx = tid + p * 256;
            if (idx < 640) {
                int n  = idx >> 4;
                int kk = idx & 15;
                float w = W[n * KK + k0 + kk];
                Ws2[kk][n] = make_float2(w, w);
            }
        }
        __syncthreads();

        // This phase handles k = k0+phase and k0+phase+8 (ascending -> chain order ok)
        #pragma unroll
        for (int half = 0; half < 2; ++half) {
            const int k = phase + half * 8;
            ulonglong2 A0 = *reinterpret_cast<const ulonglong2*>(&As[k][wrow * 8]);
            ulonglong2 A1 = *reinterpret_cast<const ulonglong2*>(&As[k][wrow * 8 + 4]);
            unsigned long long b[10];
            #pragma unroll
            for (int c = 0; c < 10; ++c)
                b[c] = *reinterpret_cast<const unsigned long long*>(
                    &Ws2[k][wcol * 10 + c]);
            #pragma unroll
            for (int c = 0; c < 10; ++c) {
                fma2(acc[0][c], A0.x, b[c]);
                fma2(acc[1][c], A0.y, b[c]);
                fma2(acc[2][c], A1.x, b[c]);
                fma2(acc[3][c], A1.y, b[c]);
            }
        }
    }

    // Cross-phase combine: butterfly xor {4,1,2} == exact pairwise tree
    //   ((c0+c4)+(c1+c5)) + ((c2+c6)+(c3+c7))
    #pragma unroll
    for (int i = 0; i < 4; ++i) {
        #pragma unroll
        for (int c = 0; c < 10; ++c) {
            unsigned long long v = acc[i][c];
            v = add2(v, __shfl_xor_sync(0xFFFFFFFFu, v, 4));
            v = add2(v, __shfl_xor_sync(0xFFFFFFFFu, v, 1));
            v = add2(v, __shfl_xor_sync(0xFFFFFFFFu, v, 2));
            if (phase == 0) {
                const int n  = wcol * 10 + c;
                const int m0 = mbase + wrow * 8 + i * 2;
                g_cur[(size_t)m0 * NN + n] =
                    __uint_as_float((unsigned int)(v & 0xFFFFFFFFu));
                g_cur[(size_t)(m0 + 1) * NN + n] =
                    __uint_as_float((unsigned int)(v >> 32));
            }
        }
    }
}

// ---------------------------------------------------------------------------
// Kernel 2: LIF recurrence over t for each of 10240 (b, n) cells.
//   reset = (mem_prev > 1); mem = (0.95*mem_prev + cur) * (1 - reset);
//   spk = (mem > 1)  [sign-exact vs (mem-1 > 0) via Sterbenz]
// mul+add kept un-fused (__fmul_rn/__fadd_rn), matching the reference.
// 64-thread blocks -> 160 blocks -> all 148 SMs busy (was 80 blocks/128thr).
// Ring-buffer prefetch (depth 16) hides L2 latency on the per-t loads.
// ---------------------------------------------------------------------------
__global__ __launch_bounds__(64)
void snn_scan_kernel(float* __restrict__ out) {
    const int idx = blockIdx.x * 64 + threadIdx.x;    // < 10240
    const float* __restrict__ cp = g_cur + idx;
    float* __restrict__ sp = out + idx;               // spk_rec
    float* __restrict__ mp = out + OUT_HALF + idx;    // mem_rec

    float buf[16];
    #pragma unroll
    for (int i = 0; i < 16; ++i) buf[i] = cp[(size_t)i * PLANE];

    float m = 0.0f;

    for (int t0 = 0; t0 < 240; t0 += 16) {
        #pragma unroll
        for (int u = 0; u < 16; ++u) {
            int t = t0 + u;
            float c = buf[u];
            int tn = t + 16; if (tn > TT - 1) tn = TT - 1;
            buf[u] = cp[(size_t)tn * PLANE];
            float r = (m > 1.0f) ? 0.0f : 1.0f;
            m = __fmul_rn(__fadd_rn(__fmul_rn(0.95f, m), c), r);
            sp[(size_t)t * PLANE] = (m > 1.0f) ? 1.0f : 0.0f;
            mp[(size_t)t * PLANE] = m;
        }
    }
    #pragma unroll
    for (int u = 0; u < 15; ++u) {
        int t = 240 + u;
        float c = buf[u];
        float r = (m > 1.0f) ? 0.0f : 1.0f;
        m = __fmul_rn(__fadd_rn(__fmul_rn(0.95f, m), c), r);
        sp[(size_t)t * PLANE] = (m > 1.0f) ? 1.0f : 0.0f;
        mp[(size_t)t * PLANE] = m;
    }
}

// ---------------------------------------------------------------------------
extern "C" void kernel_launch(void* const* d_in, const int* in_sizes, int n_in,
                              void* d_out, int out_size) {
    const float* x = (const float*)d_in[0];
    const float* W = (const float*)d_in[1];
    // Defensive: metadata order should be (x, W); swap if sizes say otherwise.
    if (n_in >= 2 && in_sizes[0] == NN * KK) {
        const float* t = x; x = W; W = t;
    }
    float* out = (float*)d_out;

    snn_gemm_kernel<<<MM / 64, 256>>>(x, W);    // 1020 blocks
    snn_scan_kernel<<<PLANE / 64, 64>>>(out);   // 160 blocks
}

// round 9
// speedup vs baseline: 2.1404x; 2.1404x over previous
#include <cuda_runtime.h>
#include <cstdint>
#include <cstddef>

// Problem constants
#define TT   255
#define BB   256
#define KK   784
#define NN   40
#define MM   (TT * BB)          // 65280
#define PLANE (BB * NN)         // 10240 elements per timestep
#define OUT_HALF (TT * PLANE)   // 2,611,200

// Scratch for cur = x @ W^T   (10.44 MB, static device global: allowed)
__device__ float g_cur[(size_t)MM * NN];

// packed f32x2 FMA: d = fma(a, b, d) per lane (IEEE rn, fused)
__device__ __forceinline__ void fma2(unsigned long long& d,
                                     unsigned long long a,
                                     unsigned long long b) {
    asm("fma.rn.f32x2 %0, %1, %2, %3;" : "=l"(d) : "l"(a), "l"(b), "l"(d));
}
// packed f32x2 add (rn)
__device__ __forceinline__ unsigned long long add2(unsigned long long a,
                                                   unsigned long long b) {
    unsigned long long d;
    asm("add.rn.f32x2 %0, %1, %2;" : "=l"(d) : "l"(a), "l"(b));
    return d;
}

// ---------------------------------------------------------------------------
// Kernel 1: cur[m][n] = sum_k x[m][k] * W[n][k]
//
// Rounding scheme (bit-identical to the R7/R8-passing kernels):
//   8 chains, chain j = fused-FMA over k ≡ j (mod 8) ascending;
//   combine: ((c0+c4)+(c1+c5)) + ((c2+c6)+(c3+c7))
//   realized by phase-per-thread + butterfly shuffles xor {4,1,2}.
//
// NEW: software-pipelined double buffering.
//   iter c: STS(chunk c+1 from regs) ; LDG(chunk c+2 -> regs) ;
//           compute(chunk c) ; one __syncthreads.
// 2 CTAs/SM (launch_bounds(256,2)) for latency hiding.
//
// 256 threads = 8 phases x 32 workers (8 row-groups x TM=8, 4 col-groups x
// TN=10). BM=64, BN=40, BK=16, grid = 1020.
// As stride 68 floats (phase k -> bank 4k, conflict-free LDS.128);
// Ws2 stride 42 float2 (k -> bank 20k mod 32, distinct; 4x lane broadcast).
// ---------------------------------------------------------------------------
#define NCHUNK (KK / 16)    // 49

__global__ __launch_bounds__(256, 2)
void snn_gemm_kernel(const float* __restrict__ x, const float* __restrict__ W) {
    __shared__ float  As[2][16][68];
    __shared__ float2 Ws2[2][16][42];

    const int tid   = threadIdx.x;
    const int phase = tid & 7;          // chain index 0..7
    const int ww    = tid >> 3;         // worker 0..31
    const int wrow  = ww & 7;           // 8 row groups * TM=8 -> BM=64
    const int wcol  = ww >> 3;          // 4 col groups * TN=10 -> BN=40
    const int mbase = blockIdx.x * 64;

    // Staging-load geometry
    const int arow = tid >> 2;          // 0..63
    const int aq   = tid & 3;           // 0..3 (float4 within 16-k chunk)
    const float* __restrict__ aptr = x + (size_t)(mbase + arow) * KK + aq * 4;
    const int  wn      = tid >> 2;      // n index for W staging
    const int  wq      = tid & 3;
    const bool wactive = (tid < 160);   // 40 n * 4 quads
    const float* __restrict__ wptr = W + (size_t)wn * KK + wq * 4;

    float4 a_st, w_st = make_float4(0.f, 0.f, 0.f, 0.f);

    // ---- prologue: chunk 0 -> smem stage 0; chunk 1 -> regs ----
    a_st = *reinterpret_cast<const float4*>(aptr);
    if (wactive) w_st = *reinterpret_cast<const float4*>(wptr);
    As[0][aq * 4 + 0][arow] = a_st.x;
    As[0][aq * 4 + 1][arow] = a_st.y;
    As[0][aq * 4 + 2][arow] = a_st.z;
    As[0][aq * 4 + 3][arow] = a_st.w;
    if (wactive) {
        Ws2[0][wq * 4 + 0][wn] = make_float2(w_st.x, w_st.x);
        Ws2[0][wq * 4 + 1][wn] = make_float2(w_st.y, w_st.y);
        Ws2[0][wq * 4 + 2][wn] = make_float2(w_st.z, w_st.z);
        Ws2[0][wq * 4 + 3][wn] = make_float2(w_st.w, w_st.w);
    }
    a_st = *reinterpret_cast<const float4*>(aptr + 16);
    if (wactive) w_st = *reinterpret_cast<const float4*>(wptr + 16);
    __syncthreads();

    unsigned long long acc[4][10];
    #pragma unroll
    for (int i = 0; i < 4; ++i)
        #pragma unroll
        for (int c = 0; c < 10; ++c) acc[i][c] = 0ULL;

    for (int c = 0; c < NCHUNK; ++c) {
        const int nb = (c + 1) & 1;
        // STS chunk c+1 (in regs) into the other buffer
        if (c < NCHUNK - 1) {
            As[nb][aq * 4 + 0][arow] = a_st.x;
            As[nb][aq * 4 + 1][arow] = a_st.y;
            As[nb][aq * 4 + 2][arow] = a_st.z;
            As[nb][aq * 4 + 3][arow] = a_st.w;
            if (wactive) {
                Ws2[nb][wq * 4 + 0][wn] = make_float2(w_st.x, w_st.x);
                Ws2[nb][wq * 4 + 1][wn] = make_float2(w_st.y, w_st.y);
                Ws2[nb][wq * 4 + 2][wn] = make_float2(w_st.z, w_st.z);
                Ws2[nb][wq * 4 + 3][wn] = make_float2(w_st.w, w_st.w);
            }
        }
        // LDG chunk c+2 -> regs (in flight during compute below)
        if (c + 2 < NCHUNK) {
            a_st = *reinterpret_cast<const float4*>(aptr + (c + 2) * 16);
            if (wactive) w_st = *reinterpret_cast<const float4*>(wptr + (c + 2) * 16);
        }

        // compute chunk c from stage c&1
        const int s = c & 1;
        #pragma unroll
        for (int half = 0; half < 2; ++half) {
            const int k = phase + half * 8;     // ascending within chain
            ulonglong2 A0 = *reinterpret_cast<const ulonglong2*>(&As[s][k][wrow * 8]);
            ulonglong2 A1 = *reinterpret_cast<const ulonglong2*>(&As[s][k][wrow * 8 + 4]);
            #pragma unroll
            for (int cc = 0; cc < 10; ++cc) {
                unsigned long long b = *reinterpret_cast<const unsigned long long*>(
                    &Ws2[s][k][wcol * 10 + cc]);
                fma2(acc[0][cc], A0.x, b);
                fma2(acc[1][cc], A0.y, b);
                fma2(acc[2][cc], A1.x, b);
                fma2(acc[3][cc], A1.y, b);
            }
        }
        __syncthreads();   // single barrier: STS(c+1) visible; readers of stage s done
    }

    // Cross-phase combine: butterfly xor {4,1,2} == exact pairwise tree
    #pragma unroll
    for (int i = 0; i < 4; ++i) {
        #pragma unroll
        for (int cc = 0; cc < 10; ++cc) {
            unsigned long long v = acc[i][cc];
            v = add2(v, __shfl_xor_sync(0xFFFFFFFFu, v, 4));
            v = add2(v, __shfl_xor_sync(0xFFFFFFFFu, v, 1));
            v = add2(v, __shfl_xor_sync(0xFFFFFFFFu, v, 2));
            if (phase == 0) {
                const int n  = wcol * 10 + cc;
                const int m0 = mbase + wrow * 8 + i * 2;
                g_cur[(size_t)m0 * NN + n] =
                    __uint_as_float((unsigned int)(v & 0xFFFFFFFFu));
                g_cur[(size_t)(m0 + 1) * NN + n] =
                    __uint_as_float((unsigned int)(v >> 32));
            }
        }
    }
}

// ---------------------------------------------------------------------------
// Kernel 2: LIF recurrence; 2 cells per thread (float2 I/O, ILP 2).
//   reset = (mem_prev > 1); mem = (0.95*mem_prev + cur) * (1 - reset);
//   spk = (mem > 1)  [sign-exact vs (mem-1 > 0) via Sterbenz]
// Per-cell op order identical to the passing kernel (unfused mul/add).
// 5120 threads = 160 blocks x 32. Ring-buffer prefetch depth 16.
// ---------------------------------------------------------------------------
#define P2 (PLANE / 2)   // 5120 float2 per timestep

__global__ __launch_bounds__(32)
void snn_scan_kernel(float* __restrict__ out) {
    const int j = blockIdx.x * 32 + threadIdx.x;      // < 5120
    const float2* __restrict__ cp = reinterpret_cast<const float2*>(g_cur) + j;
    float2* __restrict__ sp = reinterpret_cast<float2*>(out) + j;
    float2* __restrict__ mp = reinterpret_cast<float2*>(out + OUT_HALF) + j;

    float2 buf[16];
    #pragma unroll
    for (int i = 0; i < 16; ++i) buf[i] = cp[(size_t)i * P2];

    float m0 = 0.0f, m1 = 0.0f;

    for (int t0 = 0; t0 < 240; t0 += 16) {
        #pragma unroll
        for (int u = 0; u < 16; ++u) {
            int t = t0 + u;
            float2 c = buf[u];
            int tn = t + 16; if (tn > TT - 1) tn = TT - 1;
            buf[u] = cp[(size_t)tn * P2];
            float r0 = (m0 > 1.0f) ? 0.0f : 1.0f;
            float r1 = (m1 > 1.0f) ? 0.0f : 1.0f;
            m0 = __fmul_rn(__fadd_rn(__fmul_rn(0.95f, m0), c.x), r0);
            m1 = __fmul_rn(__fadd_rn(__fmul_rn(0.95f, m1), c.y), r1);
            sp[(size_t)t * P2] = make_float2((m0 > 1.0f) ? 1.0f : 0.0f,
                                             (m1 > 1.0f) ? 1.0f : 0.0f);
            mp[(size_t)t * P2] = make_float2(m0, m1);
        }
    }
    #pragma unroll
    for (int u = 0; u < 15; ++u) {
        int t = 240 + u;
        float2 c = buf[u];
        float r0 = (m0 > 1.0f) ? 0.0f : 1.0f;
        float r1 = (m1 > 1.0f) ? 0.0f : 1.0f;
        m0 = __fmul_rn(__fadd_rn(__fmul_rn(0.95f, m0), c.x), r0);
        m1 = __fmul_rn(__fadd_rn(__fmul_rn(0.95f, m1), c.y), r1);
        sp[(size_t)t * P2] = make_float2((m0 > 1.0f) ? 1.0f : 0.0f,
                                         (m1 > 1.0f) ? 1.0f : 0.0f);
        mp[(size_t)t * P2] = make_float2(m0, m1);
    }
}

// ---------------------------------------------------------------------------
extern "C" void kernel_launch(void* const* d_in, const int* in_sizes, int n_in,
                              void* d_out, int out_size) {
    const float* x = (const float*)d_in[0];
    const float* W = (const float*)d_in[1];
    // Defensive: metadata order should be (x, W); swap if sizes say otherwise.
    if (n_in >= 2 && in_sizes[0] == NN * KK) {
        const float* t = x; x = W; W = t;
    }
    float* out = (float*)d_out;

    snn_gemm_kernel<<<MM / 64, 256>>>(x, W);    // 1020 blocks
    snn_scan_kernel<<<P2 / 32, 32>>>(out);      // 160 blocks
}

// round 11
// speedup vs baseline: 2.1675x; 1.0126x over previous
#include <cuda_runtime.h>
#include <cstdint>
#include <cstddef>

// Problem constants
#define TT   255
#define BB   256
#define KK   784
#define NN   40
#define MM   (TT * BB)          // 65280
#define PLANE (BB * NN)         // 10240 elements per timestep
#define OUT_HALF (TT * PLANE)   // 2,611,200

// Scratch for cur = x @ W^T   (10.44 MB, static device global: allowed)
__device__ float g_cur[(size_t)MM * NN];

// packed f32x2 FMA: d = fma(a, b, d) per lane (IEEE rn, fused)
__device__ __forceinline__ void fma2(unsigned long long& d,
                                     unsigned long long a,
                                     unsigned long long b) {
    asm("fma.rn.f32x2 %0, %1, %2, %3;" : "=l"(d) : "l"(a), "l"(b), "l"(d));
}
// packed f32x2 add (rn)
__device__ __forceinline__ unsigned long long add2(unsigned long long a,
                                                   unsigned long long b) {
    unsigned long long d;
    asm("add.rn.f32x2 %0, %1, %2;" : "=l"(d) : "l"(a), "l"(b));
    return d;
}

// ---------------------------------------------------------------------------
// Kernel 1: cur[m][n] = sum_k x[m][k] * W[n][k]
//
// Rounding scheme (bit-identical to the R7..R9-passing kernels):
//   8 chains, chain j = fused-FMA over k ≡ j (mod 8) ascending;
//   combine: ((c0+c4)+(c1+c5)) + ((c2+c6)+(c3+c7))
//   realized by phase-per-thread + butterfly shuffles xor {4,1,2}.
//
// Software-pipelined double buffering (prefetch distance 2), 2 CTAs/SM.
// b-operands loaded as 5x LDS.128 (duplicated pairs, 16B aligned,
// full-bank 1-wavefront broadcast) instead of 10x LDS.64 -> LSU traffic
// per chunk drops ~25%, putting the FMA pipe clearly in charge.
//
// 256 threads = 8 phases x 32 workers (8 row-groups x TM=8, 4 col-groups x
// TN=10). BM=64, BN=40, BK=16, grid = 1020.
// As stride 68 floats; Ws2 stride 42 float2 (k -> bank-quad k*20 mod 32,
// all 8 quads distinct and covering all 32 banks).
// ---------------------------------------------------------------------------
#define NCHUNK (KK / 16)    // 49

__global__ __launch_bounds__(256, 2)
void snn_gemm_kernel(const float* __restrict__ x, const float* __restrict__ W) {
    __shared__ float  As[2][16][68];
    __shared__ float2 Ws2[2][16][42];

    const int tid   = threadIdx.x;
    const int phase = tid & 7;          // chain index 0..7
    const int ww    = tid >> 3;         // worker 0..31
    const int wrow  = ww & 7;           // 8 row groups * TM=8 -> BM=64
    const int wcol  = ww >> 3;          // 4 col groups * TN=10 -> BN=40
    const int mbase = blockIdx.x * 64;

    // Staging-load geometry
    const int arow = tid >> 2;          // 0..63
    const int aq   = tid & 3;           // 0..3 (float4 within 16-k chunk)
    const float* __restrict__ aptr = x + (size_t)(mbase + arow) * KK + aq * 4;
    const int  wn      = tid >> 2;      // n index for W staging
    const int  wq      = tid & 3;
    const bool wactive = (tid < 160);   // 40 n * 4 quads
    const float* __restrict__ wptr = W + (size_t)wn * KK + wq * 4;

    float4 a_st, w_st = make_float4(0.f, 0.f, 0.f, 0.f);

    // ---- prologue: chunk 0 -> smem stage 0; chunk 1 -> regs ----
    a_st = *reinterpret_cast<const float4*>(aptr);
    if (wactive) w_st = *reinterpret_cast<const float4*>(wptr);
    As[0][aq * 4 + 0][arow] = a_st.x;
    As[0][aq * 4 + 1][arow] = a_st.y;
    As[0][aq * 4 + 2][arow] = a_st.z;
    As[0][aq * 4 + 3][arow] = a_st.w;
    if (wactive) {
        Ws2[0][wq * 4 + 0][wn] = make_float2(w_st.x, w_st.x);
        Ws2[0][wq * 4 + 1][wn] = make_float2(w_st.y, w_st.y);
        Ws2[0][wq * 4 + 2][wn] = make_float2(w_st.z, w_st.z);
        Ws2[0][wq * 4 + 3][wn] = make_float2(w_st.w, w_st.w);
    }
    a_st = *reinterpret_cast<const float4*>(aptr + 16);
    if (wactive) w_st = *reinterpret_cast<const float4*>(wptr + 16);
    __syncthreads();

    unsigned long long acc[4][10];
    #pragma unroll
    for (int i = 0; i < 4; ++i)
        #pragma unroll
        for (int c = 0; c < 10; ++c) acc[i][c] = 0ULL;

    for (int c = 0; c < NCHUNK; ++c) {
        const int nb = (c + 1) & 1;
        // STS chunk c+1 (in regs) into the other buffer
        if (c < NCHUNK - 1) {
            As[nb][aq * 4 + 0][arow] = a_st.x;
            As[nb][aq * 4 + 1][arow] = a_st.y;
            As[nb][aq * 4 + 2][arow] = a_st.z;
            As[nb][aq * 4 + 3][arow] = a_st.w;
            if (wactive) {
                Ws2[nb][wq * 4 + 0][wn] = make_float2(w_st.x, w_st.x);
                Ws2[nb][wq * 4 + 1][wn] = make_float2(w_st.y, w_st.y);
                Ws2[nb][wq * 4 + 2][wn] = make_float2(w_st.z, w_st.z);
                Ws2[nb][wq * 4 + 3][wn] = make_float2(w_st.w, w_st.w);
            }
        }
        // LDG chunk c+2 -> regs (in flight during compute below)
        if (c + 2 < NCHUNK) {
            a_st = *reinterpret_cast<const float4*>(aptr + (c + 2) * 16);
            if (wactive) w_st = *reinterpret_cast<const float4*>(wptr + (c + 2) * 16);
        }

        // compute chunk c from stage c&1
        const int s = c & 1;
        #pragma unroll
        for (int half = 0; half < 2; ++half) {
            const int k = phase + half * 8;     // ascending within chain
            ulonglong2 A0 = *reinterpret_cast<const ulonglong2*>(&As[s][k][wrow * 8]);
            ulonglong2 A1 = *reinterpret_cast<const ulonglong2*>(&As[s][k][wrow * 8 + 4]);
            // 5x LDS.128: duplicated-pair b operands {0,1},{2,3},{4,5},{6,7},{8,9}
            const float2* bp = &Ws2[s][k][wcol * 10];
            ulonglong2 B01 = *reinterpret_cast<const ulonglong2*>(bp + 0);
            ulonglong2 B23 = *reinterpret_cast<const ulonglong2*>(bp + 2);
            ulonglong2 B45 = *reinterpret_cast<const ulonglong2*>(bp + 4);
            ulonglong2 B67 = *reinterpret_cast<const ulonglong2*>(bp + 6);
            ulonglong2 B89 = *reinterpret_cast<const ulonglong2*>(bp + 8);
            unsigned long long b[10] = { B01.x, B01.y, B23.x, B23.y, B45.x,
                                         B45.y, B67.x, B67.y, B89.x, B89.y };
            #pragma unroll
            for (int cc = 0; cc < 10; ++cc) {
                fma2(acc[0][cc], A0.x, b[cc]);
                fma2(acc[1][cc], A0.y, b[cc]);
                fma2(acc[2][cc], A1.x, b[cc]);
                fma2(acc[3][cc], A1.y, b[cc]);
            }
        }
        __syncthreads();   // single barrier: STS(c+1) visible; readers of stage s done
    }

    // Cross-phase combine: butterfly xor {4,1,2} == exact pairwise tree
    #pragma unroll
    for (int i = 0; i < 4; ++i) {
        #pragma unroll
        for (int cc = 0; cc < 10; ++cc) {
            unsigned long long v = acc[i][cc];
            v = add2(v, __shfl_xor_sync(0xFFFFFFFFu, v, 4));
            v = add2(v, __shfl_xor_sync(0xFFFFFFFFu, v, 1));
            v = add2(v, __shfl_xor_sync(0xFFFFFFFFu, v, 2));
            if (phase == 0) {
                const int n  = wcol * 10 + cc;
                const int m0 = mbase + wrow * 8 + i * 2;
                g_cur[(size_t)m0 * NN + n] =
                    __uint_as_float((unsigned int)(v & 0xFFFFFFFFu));
                g_cur[(size_t)(m0 + 1) * NN + n] =
                    __uint_as_float((unsigned int)(v >> 32));
            }
        }
    }
}

// ---------------------------------------------------------------------------
// Kernel 2: LIF recurrence; 2 cells per thread (float2 I/O, ILP 2).
//   mem_new = (0.95*mem + cur) * (1 - (mem>1))
//           == select(mem > 1, 0, unfused(0.95*mem + cur))
//   (only delta vs multiply: -0 -> +0 on reset steps; zero error, and
//    beta*(+-0)+c == c either way, so the recurrence is identical)
//   spk = (mem_new > 1)  [sign-exact vs (mem-1 > 0) via Sterbenz]
// Select form keeps FSETP off the arithmetic path: ~17 cyc/step vs ~25.
// Ring-buffer prefetch depth 16 hides L2 latency.
// ---------------------------------------------------------------------------
#define P2 (PLANE / 2)   // 5120 float2 per timestep

__global__ __launch_bounds__(32)
void snn_scan_kernel(float* __restrict__ out) {
    const int j = blockIdx.x * 32 + threadIdx.x;      // < 5120
    const float2* __restrict__ cp = reinterpret_cast<const float2*>(g_cur) + j;
    float2* __restrict__ sp = reinterpret_cast<float2*>(out) + j;
    float2* __restrict__ mp = reinterpret_cast<float2*>(out + OUT_HALF) + j;

    float2 buf[16];
    #pragma unroll
    for (int i = 0; i < 16; ++i) buf[i] = cp[(size_t)i * P2];

    float m0 = 0.0f, m1 = 0.0f;

    for (int t0 = 0; t0 < 240; t0 += 16) {
        #pragma unroll
        for (int u = 0; u < 16; ++u) {
            int t = t0 + u;
            float2 c = buf[u];
            int tn = t + 16; if (tn > TT - 1) tn = TT - 1;
            buf[u] = cp[(size_t)tn * P2];
            float n0 = __fadd_rn(__fmul_rn(0.95f, m0), c.x);
            float n1 = __fadd_rn(__fmul_rn(0.95f, m1), c.y);
            m0 = (m0 > 1.0f) ? 0.0f : n0;
            m1 = (m1 > 1.0f) ? 0.0f : n1;
            sp[(size_t)t * P2] = make_float2((m0 > 1.0f) ? 1.0f : 0.0f,
                                             (m1 > 1.0f) ? 1.0f : 0.0f);
            mp[(size_t)t * P2] = make_float2(m0, m1);
        }
    }
    #pragma unroll
    for (int u = 0; u < 15; ++u) {
        int t = 240 + u;
        float2 c = buf[u];
        float n0 = __fadd_rn(__fmul_rn(0.95f, m0), c.x);
        float n1 = __fadd_rn(__fmul_rn(0.95f, m1), c.y);
        m0 = (m0 > 1.0f) ? 0.0f : n0;
        m1 = (m1 > 1.0f) ? 0.0f : n1;
        sp[(size_t)t * P2] = make_float2((m0 > 1.0f) ? 1.0f : 0.0f,
                                         (m1 > 1.0f) ? 1.0f : 0.0f);
        mp[(size_t)t * P2] = make_float2(m0, m1);
    }
}

// ---------------------------------------------------------------------------
extern "C" void kernel_launch(void* const* d_in, const int* in_sizes, int n_in,
                              void* d_out, int out_size) {
    const float* x = (const float*)d_in[0];
    const float* W = (const float*)d_in[1];
    // Defensive: metadata order should be (x, W); swap if sizes say otherwise.
    if (n_in >= 2 && in_sizes[0] == NN * KK) {
        const float* t = x; x = W; W = t;
    }
    float* out = (float*)d_out;

    snn_gemm_kernel<<<MM / 64, 256>>>(x, W);    // 1020 blocks
    snn_scan_kernel<<<P2 / 32, 32>>>(out);      // 160 blocks
}